// round 3
// baseline (speedup 1.0000x reference)
#include <cuda_runtime.h>

// Problem constants
#define Nn 4
#define Mm 1024
#define Dd 64
#define Ll 16
#define Bb 4096
#define BL 65536           // Bb * Ll
#define DECAYF 0.999f
#define EPSF 1e-5f
#define COMMITF 0.05f

// Output layout (all fp32, concatenated in reference-return order)
#define OFF_ZQ   0LL
#define OFF_LOSS 16777216LL
#define OFF_PERP 16777217LL
#define OFF_IDX  16777218LL   // (B, N, L) as floats
#define OFF_EZQ  17039362LL   // identical values to z_q
#define OFF_EMB  33816578LL
#define OFF_CNT  34078722LL
#define OFF_EMW  34082818LL

// Device scratch (static allocation only — no cudaMalloc allowed)
__device__ float g_xt[Nn * BL * Dd];      // x transposed to (n, k, d) contiguous
__device__ float g_xnorm[Nn * BL];        // ||x_k||^2, reference rounding
__device__ int   g_idx[Nn * BL];          // argmin indices
__device__ float g_dw[Nn * Mm * Dd];      // scatter accumulator
__device__ int   g_cnt[Nn * Mm];          // histogram
__device__ float g_enorm[Nn * Mm];        // ||e||^2, reference rounding
__device__ float g_fcnt[Nn * Mm];         // final (laplace-smoothed) counts
__device__ float g_losspart[Bb * Nn];     // per-block loss partials

// ---------------------------------------------------------------------------
__global__ void k_zero() {
    int i = blockIdx.x * 256 + threadIdx.x;          // grid 1024 x 256 = 262144
    if (i < Nn * Mm * Dd) g_dw[i] = 0.0f;
    if (i < Nn * Mm)      g_cnt[i] = 0;
}

// ---------------------------------------------------------------------------
// Transpose x (B, N*D*L) -> g_xt (N, BL, D), and compute ||x||^2 per row with
// the exact reference rounding: sequential sum of individually-rounded squares.
__global__ void k_transpose(const float* __restrict__ x) {
    __shared__ float s[16][65];   // s[l][d]
    int bn = blockIdx.x;
    int b = bn >> 2, n = bn & 3;
    int t = threadIdx.x;
    const float4* xp = (const float4*)(x + (long long)b * 4096 + n * 1024);
    float4 v = xp[t];                      // lin = 4t : d = t>>2, l = (t&3)*4 .. +3
    int d = t >> 2, lb = (t & 3) * 4;
    s[lb + 0][d] = v.x; s[lb + 1][d] = v.y; s[lb + 2][d] = v.z; s[lb + 3][d] = v.w;
    __syncthreads();
    int r = t >> 4, c = t & 15;            // row l = r, 16 float4 per row
    float4 w = make_float4(s[r][c * 4], s[r][c * 4 + 1], s[r][c * 4 + 2], s[r][c * 4 + 3]);
    ((float4*)g_xt)[((long long)n * BL + b * 16 + r) * 16 + c] = w;
    if (t < 16) {
        float acc = 0.0f;
        #pragma unroll 8
        for (int dd = 0; dd < 64; dd++) {
            float vv = s[t][dd];
            acc = __fadd_rn(acc, __fmul_rn(vv, vv));   // square rounds, then add
        }
        g_xnorm[(long long)n * BL + b * 16 + t] = acc;
    }
}

// ---------------------------------------------------------------------------
// ||e||^2 per (n, m) with reference rounding (sequential add of rounded squares)
__global__ void k_enorm(const float* __restrict__ emb) {
    int i = blockIdx.x * blockDim.x + threadIdx.x;   // 0..4095
    const float* e = emb + (long long)i * 64;
    float s = 0.0f;
    #pragma unroll 8
    for (int d = 0; d < 64; d++) {
        float v = e[d];
        s = __fadd_rn(s, __fmul_rn(v, v));
    }
    g_enorm[i] = s;
}

// ---------------------------------------------------------------------------
// Main argmin GEMM. Block 256 threads (16x16). 64 k-rows per block, M in tiles
// of 128. Thread owns 4 k x 8 m. Shared tiles stored [row][d] with stride 68
// floats (16B-aligned rows, 2-way max conflict) and read with LDS.128 (float4,
// d in steps of 4) to cut issue-slot pressure ~4x on shared loads.
// Score replicates reference bit-exactly:
//   score = fl( fl(Sx + Se) - 2*dot ),  dot = sequential-ascending-d fma chain.
#define XS_STR 68
extern __shared__ float sm_argmin[];
__global__ void k_argmin(const float* __restrict__ emb, float* __restrict__ out) {
    float* xs  = sm_argmin;                         // [64][68]
    float* es  = sm_argmin + 64 * XS_STR;           // [128][68]
    float* ens = es + 128 * XS_STR;                 // [128]
    float* xnr = ens + 128;                         // [64]
    int n = blockIdx.y;
    int kbase = blockIdx.x * 64;
    int t = threadIdx.x;
    int tx = t & 15, ty = t >> 4;

    const float* xtp = g_xt + ((long long)n * BL + kbase) * 64;
    #pragma unroll
    for (int i = 0; i < 16; i++) {
        int j = t + i * 256;                        // j = k*64 + d
        xs[(j >> 6) * XS_STR + (j & 63)] = xtp[j];
    }
    if (t < 64) xnr[t] = g_xnorm[(long long)n * BL + kbase + t];

    float bv[4]; int bi[4];
    #pragma unroll
    for (int i = 0; i < 4; i++) { bv[i] = 3.4e38f; bi[i] = 0; }

    __syncthreads();
    float xnreg[4];
    #pragma unroll
    for (int i = 0; i < 4; i++) xnreg[i] = xnr[i * 16 + ty];

    for (int mt = 0; mt < 8; mt++) {
        int mbase = mt * 128;
        const float* ep = emb + ((long long)n * Mm + mbase) * 64;
        __syncthreads();
        #pragma unroll
        for (int i = 0; i < 32; i++) {
            int j = t + i * 256;                    // j = m*64 + d
            es[(j >> 6) * XS_STR + (j & 63)] = ep[j];
        }
        if (t < 128) ens[t] = g_enorm[n * Mm + mbase + t];
        __syncthreads();

        float acc[4][8];
        #pragma unroll
        for (int i = 0; i < 4; i++)
            #pragma unroll
            for (int j = 0; j < 8; j++) acc[i][j] = 0.0f;

        #pragma unroll 4
        for (int d4 = 0; d4 < 64; d4 += 4) {
            float4 er4[8];
            #pragma unroll
            for (int j = 0; j < 8; j++)
                er4[j] = *(const float4*)&es[(j * 16 + tx) * XS_STR + d4];
            #pragma unroll
            for (int i = 0; i < 4; i++) {
                float4 x4 = *(const float4*)&xs[(i * 16 + ty) * XS_STR + d4];
                #pragma unroll
                for (int j = 0; j < 8; j++) {
                    acc[i][j] = __fmaf_rn(x4.x, er4[j].x, acc[i][j]);
                    acc[i][j] = __fmaf_rn(x4.y, er4[j].y, acc[i][j]);
                    acc[i][j] = __fmaf_rn(x4.z, er4[j].z, acc[i][j]);
                    acc[i][j] = __fmaf_rn(x4.w, er4[j].w, acc[i][j]);
                }
            }
        }

        // reference-exact score + running argmin (m ascending => '<' keeps first)
        #pragma unroll
        for (int j = 0; j < 8; j++) {
            int ml = j * 16 + tx;
            float en = ens[ml];
            int mg = mbase + ml;
            #pragma unroll
            for (int i = 0; i < 4; i++) {
                float t1 = __fadd_rn(xnreg[i], en);
                float sc = __fadd_rn(t1, __fmul_rn(-2.0f, acc[i][j]));
                if (sc < bv[i]) { bv[i] = sc; bi[i] = mg; }
            }
        }
    }
    __syncthreads();

    // cross-thread reduction over the 16 tx lanes per k (tie -> lowest index)
    float* rv = sm_argmin;                  // [64][16]
    int*   ri = (int*)(sm_argmin + 1024);   // [64][16]
    #pragma unroll
    for (int i = 0; i < 4; i++) {
        rv[(i * 16 + ty) * 16 + tx] = bv[i];
        ri[(i * 16 + ty) * 16 + tx] = bi[i];
    }
    __syncthreads();
    if (t < 64) {
        float best = rv[t * 16]; int besti = ri[t * 16];
        #pragma unroll
        for (int q = 1; q < 16; q++) {
            float v = rv[t * 16 + q]; int ii = ri[t * 16 + q];
            if (v < best || (v == best && ii < besti)) { best = v; besti = ii; }
        }
        int kg = kbase + t;
        g_idx[n * BL + kg] = besti;
        atomicAdd(&g_cnt[n * Mm + besti], 1);
        int b = kg >> 4, l = kg & 15;
        out[OFF_IDX + ((long long)b * Nn + n) * Ll + l] = (float)besti;
    }
}

// ---------------------------------------------------------------------------
// dw[n, m, :] += x_flat[n, k, :] for each k with idx==m. One warp per row.
__global__ void k_dw() {
    int gw = (blockIdx.x * blockDim.x + threadIdx.x) >> 5;
    int lane = threadIdx.x & 31;
    if (gw >= Nn * BL) return;
    int n = gw >> 16;
    int m = g_idx[gw];
    const float* xr = g_xt + (long long)gw * 64;
    float* dwp = g_dw + ((long long)n * Mm + m) * 64;
    atomicAdd(dwp + lane,      xr[lane]);
    atomicAdd(dwp + lane + 32, xr[lane + 32]);
}

// ---------------------------------------------------------------------------
// EMA counts + laplace smoothing + perplexity. One block, 1024 threads (m=t).
__global__ void k_ema(const float* __restrict__ ema_count, float* __restrict__ out) {
    __shared__ float red[1024];
    int t = threadIdx.x;
    float perp = 0.0f;
    for (int n = 0; n < 4; n++) {
        float c = (float)g_cnt[n * Mm + t];
        float raw = DECAYF * ema_count[n * Mm + t] + (1.0f - DECAYF) * c;
        red[t] = raw; __syncthreads();
        for (int s = 512; s > 0; s >>= 1) { if (t < s) red[t] += red[t + s]; __syncthreads(); }
        float nsum = red[0]; __syncthreads();
        float fin = (raw + EPSF) / (nsum + Mm * EPSF) * nsum;
        out[OFF_CNT + n * Mm + t] = fin;
        g_fcnt[n * Mm + t] = fin;
        float avg = c * (1.0f / 65536.0f);
        float term = avg * logf(avg + 1e-10f);
        red[t] = term; __syncthreads();
        for (int s = 512; s > 0; s >>= 1) { if (t < s) red[t] += red[t + s]; __syncthreads(); }
        if (t == 0) perp += expf(-red[0]);
        __syncthreads();
    }
    if (t == 0) out[OFF_PERP] = perp;
}

// ---------------------------------------------------------------------------
// new_ema_weight and new_embedding
__global__ void k_weight(const float* __restrict__ ema_weight, float* __restrict__ out) {
    int i = blockIdx.x * 256 + threadIdx.x;          // < 262144
    float w = DECAYF * ema_weight[i] + (1.0f - DECAYF) * g_dw[i];
    out[OFF_EMW + i] = w;
    out[OFF_EMB + i] = w / g_fcnt[i >> 6];
}

// ---------------------------------------------------------------------------
// Gather quantized vectors, write z_q & encodings_zq, loss partials.
__global__ void k_gather(const float* __restrict__ x, const float* __restrict__ emb,
                         float* __restrict__ out) {
    __shared__ float se[16][68];    // se[l][d]
    __shared__ float red[256];
    int bn = blockIdx.x;
    int b = bn >> 2, n = bn & 3;
    int t = threadIdx.x;
    int r = t >> 4, c = t & 15;
    int idx = g_idx[n * BL + b * 16 + r];
    const float4* ep = (const float4*)emb + ((long long)n * Mm + idx) * 16;
    float4 v = ep[c];
    se[r][c * 4] = v.x; se[r][c * 4 + 1] = v.y; se[r][c * 4 + 2] = v.z; se[r][c * 4 + 3] = v.w;
    __syncthreads();
    long long base = (long long)b * 4096 + n * 1024;
    float4 xv = ((const float4*)(x + base))[t];
    int lin = t * 4;                             // lin = d*16 + l
    int d = lin >> 4, l0 = lin & 15;
    float q0 = se[l0 + 0][d], q1 = se[l0 + 1][d], q2 = se[l0 + 2][d], q3 = se[l0 + 3][d];
    ((float4*)(out + OFF_ZQ + base))[t] = make_float4(q0, q1, q2, q3);
    float2* ez = (float2*)(out + OFF_EZQ + base);   // OFF_EZQ only 8B-aligned
    ez[2 * t]     = make_float2(q0, q1);
    ez[2 * t + 1] = make_float2(q2, q3);
    float d0 = xv.x - q0, d1 = xv.y - q1, d2 = xv.z - q2, d3 = xv.w - q3;
    red[t] = d0 * d0 + d1 * d1 + d2 * d2 + d3 * d3;
    __syncthreads();
    for (int s = 128; s > 0; s >>= 1) { if (t < s) red[t] += red[t + s]; __syncthreads(); }
    if (t == 0) g_losspart[bn] = red[0];
}

// ---------------------------------------------------------------------------
__global__ void k_loss(float* __restrict__ out) {
    __shared__ float red[1024];
    int t = threadIdx.x;
    float s = 0.0f;
    for (int i = t; i < Bb * Nn; i += 1024) s += g_losspart[i];
    red[t] = s; __syncthreads();
    for (int st = 512; st > 0; st >>= 1) { if (t < st) red[t] += red[t + st]; __syncthreads(); }
    if (t == 0) out[OFF_LOSS] = COMMITF * red[0] / 16777216.0f;
}

// ---------------------------------------------------------------------------
extern "C" void kernel_launch(void* const* d_in, const int* in_sizes, int n_in,
                              void* d_out, int out_size) {
    const float* x          = (const float*)d_in[0];
    const float* emb        = (const float*)d_in[1];
    const float* ema_count  = (const float*)d_in[2];
    const float* ema_weight = (const float*)d_in[3];
    float* out = (float*)d_out;

    const int smem_bytes = (64 * XS_STR + 128 * XS_STR + 128 + 64) * 4;
    cudaFuncSetAttribute(k_argmin, cudaFuncAttributeMaxDynamicSharedMemorySize, smem_bytes);

    k_zero<<<1024, 256>>>();
    k_transpose<<<Bb * Nn, 256>>>(x);
    k_enorm<<<16, 256>>>(emb);
    dim3 ga(BL / 64, Nn);
    k_argmin<<<ga, 256, smem_bytes>>>(emb, out);
    k_dw<<<(Nn * BL) / 8, 256>>>();
    k_ema<<<1, 1024>>>(ema_count, out);
    k_weight<<<1024, 256>>>(ema_weight, out);
    k_gather<<<Bb * Nn, 256>>>(x, emb, out);
    k_loss<<<1, 1024>>>(out);
}

// round 4
// speedup vs baseline: 1.1885x; 1.1885x over previous
#include <cuda_runtime.h>

// Problem constants
#define Nn 4
#define Mm 1024
#define Dd 64
#define Ll 16
#define Bb 4096
#define BL 65536           // Bb * Ll
#define DECAYF 0.999f
#define EPSF 1e-5f
#define COMMITF 0.05f

// Output layout (all fp32, concatenated in reference-return order)
#define OFF_ZQ   0LL
#define OFF_LOSS 16777216LL
#define OFF_PERP 16777217LL
#define OFF_IDX  16777218LL   // (B, N, L) as floats
#define OFF_EZQ  17039362LL   // identical values to z_q
#define OFF_EMB  33816578LL
#define OFF_CNT  34078722LL
#define OFF_EMW  34082818LL

// Device scratch (static allocation only — no cudaMalloc allowed)
__device__ float g_xt[Nn * BL * Dd];      // x transposed to (n, k, d) contiguous
__device__ float g_xnorm[Nn * BL];        // ||x_k||^2, reference rounding
__device__ int   g_idx[Nn * BL];          // argmin indices
__device__ float g_dw[Nn * Mm * Dd];      // scatter accumulator
__device__ int   g_cnt[Nn * Mm];          // histogram
__device__ float g_enorm[Nn * Mm];        // ||e||^2, reference rounding
__device__ float g_fcnt[Nn * Mm];         // final (laplace-smoothed) counts
__device__ float g_losspart[Bb * Nn];     // per-block loss partials

// ---------------------------------------------------------------------------
__global__ void k_zero() {
    int i = blockIdx.x * 256 + threadIdx.x;          // grid 1024 x 256 = 262144
    if (i < Nn * Mm * Dd) g_dw[i] = 0.0f;
    if (i < Nn * Mm)      g_cnt[i] = 0;
}

// ---------------------------------------------------------------------------
// Transpose x (B, N*D*L) -> g_xt (N, BL, D), and compute ||x||^2 per row with
// the exact reference rounding: sequential sum of individually-rounded squares.
__global__ void k_transpose(const float* __restrict__ x) {
    __shared__ float s[16][65];   // s[l][d]
    int bn = blockIdx.x;
    int b = bn >> 2, n = bn & 3;
    int t = threadIdx.x;
    const float4* xp = (const float4*)(x + (long long)b * 4096 + n * 1024);
    float4 v = xp[t];                      // lin = 4t : d = t>>2, l = (t&3)*4 .. +3
    int d = t >> 2, lb = (t & 3) * 4;
    s[lb + 0][d] = v.x; s[lb + 1][d] = v.y; s[lb + 2][d] = v.z; s[lb + 3][d] = v.w;
    __syncthreads();
    int r = t >> 4, c = t & 15;            // row l = r, 16 float4 per row
    float4 w = make_float4(s[r][c * 4], s[r][c * 4 + 1], s[r][c * 4 + 2], s[r][c * 4 + 3]);
    ((float4*)g_xt)[((long long)n * BL + b * 16 + r) * 16 + c] = w;
    if (t < 16) {
        float acc = 0.0f;
        #pragma unroll 8
        for (int dd = 0; dd < 64; dd++) {
            float vv = s[t][dd];
            acc = __fadd_rn(acc, __fmul_rn(vv, vv));   // square rounds, then add
        }
        g_xnorm[(long long)n * BL + b * 16 + t] = acc;
    }
}

// ---------------------------------------------------------------------------
// ||e||^2 per (n, m) with reference rounding (sequential add of rounded squares)
__global__ void k_enorm(const float* __restrict__ emb) {
    int i = blockIdx.x * blockDim.x + threadIdx.x;   // 0..4095
    const float* e = emb + (long long)i * 64;
    float s = 0.0f;
    #pragma unroll 8
    for (int d = 0; d < 64; d++) {
        float v = e[d];
        s = __fadd_rn(s, __fmul_rn(v, v));
    }
    g_enorm[i] = s;
}

// ---------------------------------------------------------------------------
// Main argmin GEMM. Block 256 threads (16x16). 64 k-rows per block, M in tiles
// of 128. Thread owns 4 k x 8 m. Shared tiles stored [row][d] stride 68
// (16B-aligned rows) read via LDS.128. Loop structured so only ONE e-vector
// float4 is live at a time (regs <= 85 -> 3 CTAs/SM, enforced by launch_bounds).
// Score replicates reference bit-exactly:
//   score = fl( fl(Sx + Se) - 2*dot ),  dot = sequential-ascending-d fma chain.
#define XS_STR 68
extern __shared__ float sm_argmin[];
__global__ void __launch_bounds__(256, 3)
k_argmin(const float* __restrict__ emb, float* __restrict__ out) {
    float* xs  = sm_argmin;                         // [64][68]
    float* es  = sm_argmin + 64 * XS_STR;           // [128][68]
    float* ens = es + 128 * XS_STR;                 // [128]
    float* xnr = ens + 128;                         // [64]
    int n = blockIdx.y;
    int kbase = blockIdx.x * 64;
    int t = threadIdx.x;
    int tx = t & 15, ty = t >> 4;

    const float* xtp = g_xt + ((long long)n * BL + kbase) * 64;
    #pragma unroll
    for (int i = 0; i < 16; i++) {
        int j = t + i * 256;                        // j = k*64 + d
        xs[(j >> 6) * XS_STR + (j & 63)] = xtp[j];
    }
    if (t < 64) xnr[t] = g_xnorm[(long long)n * BL + kbase + t];

    float bv[4]; int bi[4];
    #pragma unroll
    for (int i = 0; i < 4; i++) { bv[i] = 3.4e38f; bi[i] = 0; }

    __syncthreads();
    float xnreg[4];
    #pragma unroll
    for (int i = 0; i < 4; i++) xnreg[i] = xnr[i * 16 + ty];

    for (int mt = 0; mt < 8; mt++) {
        int mbase = mt * 128;
        const float* ep = emb + ((long long)n * Mm + mbase) * 64;
        __syncthreads();
        #pragma unroll
        for (int i = 0; i < 32; i++) {
            int j = t + i * 256;                    // j = m*64 + d
            es[(j >> 6) * XS_STR + (j & 63)] = ep[j];
        }
        if (t < 128) ens[t] = g_enorm[n * Mm + mbase + t];
        __syncthreads();

        float acc[4][8];
        #pragma unroll
        for (int i = 0; i < 4; i++)
            #pragma unroll
            for (int j = 0; j < 8; j++) acc[i][j] = 0.0f;

        #pragma unroll 2
        for (int d4 = 0; d4 < 64; d4 += 4) {
            float4 x4[4];
            #pragma unroll
            for (int i = 0; i < 4; i++)
                x4[i] = *(const float4*)&xs[(i * 16 + ty) * XS_STR + d4];
            #pragma unroll
            for (int j = 0; j < 8; j++) {
                float4 e4 = *(const float4*)&es[(j * 16 + tx) * XS_STR + d4];
                #pragma unroll
                for (int i = 0; i < 4; i++) {
                    acc[i][j] = __fmaf_rn(x4[i].x, e4.x, acc[i][j]);
                    acc[i][j] = __fmaf_rn(x4[i].y, e4.y, acc[i][j]);
                    acc[i][j] = __fmaf_rn(x4[i].z, e4.z, acc[i][j]);
                    acc[i][j] = __fmaf_rn(x4[i].w, e4.w, acc[i][j]);
                }
            }
        }

        // reference-exact score + running argmin (m ascending => '<' keeps first)
        #pragma unroll
        for (int j = 0; j < 8; j++) {
            int ml = j * 16 + tx;
            float en = ens[ml];
            int mg = mbase + ml;
            #pragma unroll
            for (int i = 0; i < 4; i++) {
                float t1 = __fadd_rn(xnreg[i], en);
                float sc = __fadd_rn(t1, __fmul_rn(-2.0f, acc[i][j]));
                if (sc < bv[i]) { bv[i] = sc; bi[i] = mg; }
            }
        }
    }
    __syncthreads();

    // cross-thread reduction over the 16 tx lanes per k (tie -> lowest index)
    float* rv = sm_argmin;                  // [64][16]
    int*   ri = (int*)(sm_argmin + 1024);   // [64][16]
    #pragma unroll
    for (int i = 0; i < 4; i++) {
        rv[(i * 16 + ty) * 16 + tx] = bv[i];
        ri[(i * 16 + ty) * 16 + tx] = bi[i];
    }
    __syncthreads();
    if (t < 64) {
        float best = rv[t * 16]; int besti = ri[t * 16];
        #pragma unroll
        for (int q = 1; q < 16; q++) {
            float v = rv[t * 16 + q]; int ii = ri[t * 16 + q];
            if (v < best || (v == best && ii < besti)) { best = v; besti = ii; }
        }
        int kg = kbase + t;
        g_idx[n * BL + kg] = besti;
        atomicAdd(&g_cnt[n * Mm + besti], 1);
        int b = kg >> 4, l = kg & 15;
        out[OFF_IDX + ((long long)b * Nn + n) * Ll + l] = (float)besti;
    }
}

// ---------------------------------------------------------------------------
// dw[n, m, :] += x_flat[n, k, :] for each k with idx==m. One warp per row.
__global__ void k_dw() {
    int gw = (blockIdx.x * blockDim.x + threadIdx.x) >> 5;
    int lane = threadIdx.x & 31;
    if (gw >= Nn * BL) return;
    int n = gw >> 16;
    int m = g_idx[gw];
    const float* xr = g_xt + (long long)gw * 64;
    float* dwp = g_dw + ((long long)n * Mm + m) * 64;
    atomicAdd(dwp + lane,      xr[lane]);
    atomicAdd(dwp + lane + 32, xr[lane + 32]);
}

// ---------------------------------------------------------------------------
// EMA counts + laplace smoothing + perplexity. One block, 1024 threads (m=t).
__global__ void k_ema(const float* __restrict__ ema_count, float* __restrict__ out) {
    __shared__ float red[1024];
    int t = threadIdx.x;
    float perp = 0.0f;
    for (int n = 0; n < 4; n++) {
        float c = (float)g_cnt[n * Mm + t];
        float raw = DECAYF * ema_count[n * Mm + t] + (1.0f - DECAYF) * c;
        red[t] = raw; __syncthreads();
        for (int s = 512; s > 0; s >>= 1) { if (t < s) red[t] += red[t + s]; __syncthreads(); }
        float nsum = red[0]; __syncthreads();
        float fin = (raw + EPSF) / (nsum + Mm * EPSF) * nsum;
        out[OFF_CNT + n * Mm + t] = fin;
        g_fcnt[n * Mm + t] = fin;
        float avg = c * (1.0f / 65536.0f);
        float term = avg * logf(avg + 1e-10f);
        red[t] = term; __syncthreads();
        for (int s = 512; s > 0; s >>= 1) { if (t < s) red[t] += red[t + s]; __syncthreads(); }
        if (t == 0) perp += expf(-red[0]);
        __syncthreads();
    }
    if (t == 0) out[OFF_PERP] = perp;
}

// ---------------------------------------------------------------------------
// new_ema_weight and new_embedding
__global__ void k_weight(const float* __restrict__ ema_weight, float* __restrict__ out) {
    int i = blockIdx.x * 256 + threadIdx.x;          // < 262144
    float w = DECAYF * ema_weight[i] + (1.0f - DECAYF) * g_dw[i];
    out[OFF_EMW + i] = w;
    out[OFF_EMB + i] = w / g_fcnt[i >> 6];
}

// ---------------------------------------------------------------------------
// Gather quantized vectors, write z_q & encodings_zq, loss partials.
__global__ void k_gather(const float* __restrict__ x, const float* __restrict__ emb,
                         float* __restrict__ out) {
    __shared__ float se[16][68];    // se[l][d]
    __shared__ float red[256];
    int bn = blockIdx.x;
    int b = bn >> 2, n = bn & 3;
    int t = threadIdx.x;
    int r = t >> 4, c = t & 15;
    int idx = g_idx[n * BL + b * 16 + r];
    const float4* ep = (const float4*)emb + ((long long)n * Mm + idx) * 16;
    float4 v = ep[c];
    se[r][c * 4] = v.x; se[r][c * 4 + 1] = v.y; se[r][c * 4 + 2] = v.z; se[r][c * 4 + 3] = v.w;
    __syncthreads();
    long long base = (long long)b * 4096 + n * 1024;
    float4 xv = ((const float4*)(x + base))[t];
    int lin = t * 4;                             // lin = d*16 + l
    int d = lin >> 4, l0 = lin & 15;
    float q0 = se[l0 + 0][d], q1 = se[l0 + 1][d], q2 = se[l0 + 2][d], q3 = se[l0 + 3][d];
    ((float4*)(out + OFF_ZQ + base))[t] = make_float4(q0, q1, q2, q3);
    float2* ez = (float2*)(out + OFF_EZQ + base);   // OFF_EZQ only 8B-aligned
    ez[2 * t]     = make_float2(q0, q1);
    ez[2 * t + 1] = make_float2(q2, q3);
    float d0 = xv.x - q0, d1 = xv.y - q1, d2 = xv.z - q2, d3 = xv.w - q3;
    red[t] = d0 * d0 + d1 * d1 + d2 * d2 + d3 * d3;
    __syncthreads();
    for (int s = 128; s > 0; s >>= 1) { if (t < s) red[t] += red[t + s]; __syncthreads(); }
    if (t == 0) g_losspart[bn] = red[0];
}

// ---------------------------------------------------------------------------
__global__ void k_loss(float* __restrict__ out) {
    __shared__ float red[1024];
    int t = threadIdx.x;
    float s = 0.0f;
    for (int i = t; i < Bb * Nn; i += 1024) s += g_losspart[i];
    red[t] = s; __syncthreads();
    for (int st = 512; st > 0; st >>= 1) { if (t < st) red[t] += red[t + st]; __syncthreads(); }
    if (t == 0) out[OFF_LOSS] = COMMITF * red[0] / 16777216.0f;
}

// ---------------------------------------------------------------------------
extern "C" void kernel_launch(void* const* d_in, const int* in_sizes, int n_in,
                              void* d_out, int out_size) {
    const float* x          = (const float*)d_in[0];
    const float* emb        = (const float*)d_in[1];
    const float* ema_count  = (const float*)d_in[2];
    const float* ema_weight = (const float*)d_in[3];
    float* out = (float*)d_out;

    const int smem_bytes = (64 * XS_STR + 128 * XS_STR + 128 + 64) * 4;
    cudaFuncSetAttribute(k_argmin, cudaFuncAttributeMaxDynamicSharedMemorySize, smem_bytes);

    k_zero<<<1024, 256>>>();
    k_transpose<<<Bb * Nn, 256>>>(x);
    k_enorm<<<16, 256>>>(emb);
    dim3 ga(BL / 64, Nn);
    k_argmin<<<ga, 256, smem_bytes>>>(emb, out);
    k_dw<<<(Nn * BL) / 8, 256>>>();
    k_ema<<<1, 1024>>>(ema_count, out);
    k_weight<<<1024, 256>>>(ema_weight, out);
    k_gather<<<Bb * Nn, 256>>>(x, emb, out);
    k_loss<<<1, 1024>>>(out);
}

// round 5
// speedup vs baseline: 1.1974x; 1.0075x over previous
#include <cuda_runtime.h>
#include <cstdint>

// Problem constants
#define Nn 4
#define Mm 1024
#define Dd 64
#define Ll 16
#define Bb 4096
#define BL 65536           // Bb * Ll
#define DECAYF 0.999f
#define EPSF 1e-5f
#define COMMITF 0.05f

// Output layout (all fp32, concatenated in reference-return order)
#define OFF_ZQ   0LL
#define OFF_LOSS 16777216LL
#define OFF_PERP 16777217LL
#define OFF_IDX  16777218LL   // (B, N, L) as floats
#define OFF_EZQ  17039362LL   // identical values to z_q
#define OFF_EMB  33816578LL
#define OFF_CNT  34078722LL
#define OFF_EMW  34082818LL

// Device scratch (static allocation only — no cudaMalloc allowed)
__device__ float g_xt[Nn * BL * Dd];      // x transposed to (n, k, d) contiguous
__device__ float g_xnorm[Nn * BL];        // ||x_k||^2, reference rounding
__device__ int   g_idx[Nn * BL];          // argmin indices
__device__ float g_dw[Nn * Mm * Dd];      // scatter accumulator
__device__ int   g_cnt[Nn * Mm];          // histogram
__device__ float g_enorm[Nn * Mm];        // ||e||^2, reference rounding
__device__ float g_fcnt[Nn * Mm];         // final (laplace-smoothed) counts
__device__ float g_losspart[Bb * Nn];     // per-block loss partials

// cp.async helpers
#define CP_ASYNC16(dst, src) \
    asm volatile("cp.async.cg.shared.global [%0], [%1], 16;" :: "r"(dst), "l"(src))
#define CP_ASYNC4(dst, src) \
    asm volatile("cp.async.ca.shared.global [%0], [%1], 4;" :: "r"(dst), "l"(src))
#define CP_COMMIT() asm volatile("cp.async.commit_group;" ::: "memory")
#define CP_WAIT(nconst) asm volatile("cp.async.wait_group %0;" :: "n"(nconst) : "memory")

// ---------------------------------------------------------------------------
__global__ void k_zero() {
    int i = blockIdx.x * 256 + threadIdx.x;          // grid 1024 x 256 = 262144
    if (i < Nn * Mm * Dd) g_dw[i] = 0.0f;
    if (i < Nn * Mm)      g_cnt[i] = 0;
}

// ---------------------------------------------------------------------------
// Transpose x (B, N*D*L) -> g_xt (N, BL, D), and compute ||x||^2 per row with
// the exact reference rounding: sequential sum of individually-rounded squares.
__global__ void k_transpose(const float* __restrict__ x) {
    __shared__ float s[16][65];   // s[l][d]
    int bn = blockIdx.x;
    int b = bn >> 2, n = bn & 3;
    int t = threadIdx.x;
    const float4* xp = (const float4*)(x + (long long)b * 4096 + n * 1024);
    float4 v = xp[t];                      // lin = 4t : d = t>>2, l = (t&3)*4 .. +3
    int d = t >> 2, lb = (t & 3) * 4;
    s[lb + 0][d] = v.x; s[lb + 1][d] = v.y; s[lb + 2][d] = v.z; s[lb + 3][d] = v.w;
    __syncthreads();
    int r = t >> 4, c = t & 15;            // row l = r, 16 float4 per row
    float4 w = make_float4(s[r][c * 4], s[r][c * 4 + 1], s[r][c * 4 + 2], s[r][c * 4 + 3]);
    ((float4*)g_xt)[((long long)n * BL + b * 16 + r) * 16 + c] = w;
    if (t < 16) {
        float acc = 0.0f;
        #pragma unroll 8
        for (int dd = 0; dd < 64; dd++) {
            float vv = s[t][dd];
            acc = __fadd_rn(acc, __fmul_rn(vv, vv));   // square rounds, then add
        }
        g_xnorm[(long long)n * BL + b * 16 + t] = acc;
    }
}

// ---------------------------------------------------------------------------
// ||e||^2 per (n, m) with reference rounding (sequential add of rounded squares)
__global__ void k_enorm(const float* __restrict__ emb) {
    int i = blockIdx.x * blockDim.x + threadIdx.x;   // 0..4095
    const float* e = emb + (long long)i * 64;
    float s = 0.0f;
    #pragma unroll 8
    for (int d = 0; d < 64; d++) {
        float v = e[d];
        s = __fadd_rn(s, __fmul_rn(v, v));
    }
    g_enorm[i] = s;
}

// ---------------------------------------------------------------------------
// Main argmin GEMM, cp.async double-buffered.
// Block 256 threads (tx=m 16, ty=k 16). 128 k-rows per block; M swept in 16
// tiles of 64 codes, next tile prefetched with cp.async while current computes.
// Thread tile: 8 k (rows i*16+ty) x 4 m (cols j*16+tx).
// Shared rows stride 68 floats (16B-aligned, LDS.128-friendly).
// Score replicates reference bit-exactly:
//   score = fl( fl(Sx + Se) - 2*dot ),  dot = sequential-ascending-d fma chain.
#define XS_STR 68
#define SM_XS   0
#define SM_ES   (128 * XS_STR)                 // 2 buffers of [64][68]
#define SM_ENS  (SM_ES + 2 * 64 * XS_STR)      // 2 buffers of [64]
#define SM_XNR  (SM_ENS + 128)                 // [128]
#define SM_TOT  (SM_XNR + 128)                 // 17664 floats = 70656 B

extern __shared__ float sm_argmin[];
__global__ void __launch_bounds__(256, 3)
k_argmin(const float* __restrict__ emb, float* __restrict__ out) {
    float* xs  = sm_argmin + SM_XS;
    float* es  = sm_argmin + SM_ES;
    float* ens = sm_argmin + SM_ENS;
    float* xnr = sm_argmin + SM_XNR;
    const int n = blockIdx.y;
    const int kbase = blockIdx.x * 128;
    const int t = threadIdx.x;
    const int tx = t & 15, ty = t >> 4;

    uint32_t es_smem  = (uint32_t)__cvta_generic_to_shared(es);
    uint32_t ens_smem = (uint32_t)__cvta_generic_to_shared(ens);
    const float* embn = emb + (long long)n * Mm * 64;

    // ---- prologue: start es tile 0 fetch (async) --------------------------
    {
        const float* ep = embn;                       // tile 0
        #pragma unroll
        for (int i = 0; i < 4; i++) {
            int idx4 = t + i * 256;                   // 0..1023 float4s
            int row = idx4 >> 4, c4 = idx4 & 15;
            CP_ASYNC16(es_smem + (uint32_t)((row * XS_STR + c4 * 4) * 4),
                       (const float4*)ep + idx4);
        }
        if (t < 64) CP_ASYNC4(ens_smem + (uint32_t)(t * 4), g_enorm + n * Mm + t);
        CP_COMMIT();
    }

    // ---- load xs tile + xnorms (plain, overlaps with async fetch) ---------
    {
        const float4* xtp4 = (const float4*)(g_xt + ((long long)n * BL + kbase) * 64);
        #pragma unroll
        for (int i = 0; i < 8; i++) {
            int idx4 = t + i * 256;                   // 0..2047
            int row = idx4 >> 4, c4 = idx4 & 15;
            *(float4*)&xs[row * XS_STR + c4 * 4] = xtp4[idx4];
        }
        if (t < 128) xnr[t] = g_xnorm[(long long)n * BL + kbase + t];
    }

    float bv[8]; int bi[8];
    #pragma unroll
    for (int i = 0; i < 8; i++) { bv[i] = 3.4e38f; bi[i] = 0; }

    __syncthreads();                                  // xs/xnr visible
    float xnreg[8];
    #pragma unroll
    for (int i = 0; i < 8; i++) xnreg[i] = xnr[i * 16 + ty];

    for (int mt = 0; mt < 16; mt++) {
        int cur = mt & 1;
        // prefetch next tile into other buffer
        if (mt < 15) {
            const float* ep = embn + (mt + 1) * 64 * 64;
            uint32_t eb = es_smem + (uint32_t)((cur ^ 1) * 64 * XS_STR * 4);
            #pragma unroll
            for (int i = 0; i < 4; i++) {
                int idx4 = t + i * 256;
                int row = idx4 >> 4, c4 = idx4 & 15;
                CP_ASYNC16(eb + (uint32_t)((row * XS_STR + c4 * 4) * 4),
                           (const float4*)ep + idx4);
            }
            if (t < 64) CP_ASYNC4(ens_smem + (uint32_t)(((cur ^ 1) * 64 + t) * 4),
                                  g_enorm + n * Mm + (mt + 1) * 64 + t);
            CP_COMMIT();
            CP_WAIT(1);                               // tile mt arrived
        } else {
            CP_WAIT(0);
        }
        __syncthreads();

        const float* esb = es + cur * 64 * XS_STR;
        float acc[8][4];
        #pragma unroll
        for (int i = 0; i < 8; i++)
            #pragma unroll
            for (int j = 0; j < 4; j++) acc[i][j] = 0.0f;

        #pragma unroll 4
        for (int d4 = 0; d4 < 64; d4 += 4) {
            float4 e4[4];
            #pragma unroll
            for (int j = 0; j < 4; j++)
                e4[j] = *(const float4*)&esb[(j * 16 + tx) * XS_STR + d4];
            #pragma unroll
            for (int i = 0; i < 8; i++) {
                float4 x4 = *(const float4*)&xs[(i * 16 + ty) * XS_STR + d4];
                #pragma unroll
                for (int j = 0; j < 4; j++) {
                    acc[i][j] = __fmaf_rn(x4.x, e4[j].x, acc[i][j]);
                    acc[i][j] = __fmaf_rn(x4.y, e4[j].y, acc[i][j]);
                    acc[i][j] = __fmaf_rn(x4.z, e4[j].z, acc[i][j]);
                    acc[i][j] = __fmaf_rn(x4.w, e4[j].w, acc[i][j]);
                }
            }
        }

        // reference-exact score + running argmin (m ascending => '<' keeps first)
        #pragma unroll
        for (int j = 0; j < 4; j++) {
            int ml = j * 16 + tx;
            float en = ens[cur * 64 + ml];
            int mg = mt * 64 + ml;
            #pragma unroll
            for (int i = 0; i < 8; i++) {
                float t1 = __fadd_rn(xnreg[i], en);
                float sc = __fadd_rn(t1, __fmul_rn(-2.0f, acc[i][j]));
                if (sc < bv[i]) { bv[i] = sc; bi[i] = mg; }
            }
        }
        __syncthreads();   // all reads of buf cur done before it is refilled
    }

    // cross-thread reduction over the 16 tx lanes per k (tie -> lowest index)
    float* rv = sm_argmin;                  // [128][16]
    int*   ri = (int*)(sm_argmin + 2048);   // [128][16]
    #pragma unroll
    for (int i = 0; i < 8; i++) {
        rv[(i * 16 + ty) * 16 + tx] = bv[i];
        ri[(i * 16 + ty) * 16 + tx] = bi[i];
    }
    __syncthreads();
    if (t < 128) {
        float best = rv[t * 16]; int besti = ri[t * 16];
        #pragma unroll
        for (int q = 1; q < 16; q++) {
            float v = rv[t * 16 + q]; int ii = ri[t * 16 + q];
            if (v < best || (v == best && ii < besti)) { best = v; besti = ii; }
        }
        int kg = kbase + t;
        g_idx[n * BL + kg] = besti;
        atomicAdd(&g_cnt[n * Mm + besti], 1);
        int b = kg >> 4, l = kg & 15;
        out[OFF_IDX + ((long long)b * Nn + n) * Ll + l] = (float)besti;
    }
}

// ---------------------------------------------------------------------------
// dw[n, m, :] += x_flat[n, k, :] for each k with idx==m. One warp per row.
__global__ void k_dw() {
    int gw = (blockIdx.x * blockDim.x + threadIdx.x) >> 5;
    int lane = threadIdx.x & 31;
    if (gw >= Nn * BL) return;
    int n = gw >> 16;
    int m = g_idx[gw];
    const float* xr = g_xt + (long long)gw * 64;
    float* dwp = g_dw + ((long long)n * Mm + m) * 64;
    atomicAdd(dwp + lane,      xr[lane]);
    atomicAdd(dwp + lane + 32, xr[lane + 32]);
}

// ---------------------------------------------------------------------------
// EMA counts + laplace smoothing + perplexity. One block, 1024 threads (m=t).
__global__ void k_ema(const float* __restrict__ ema_count, float* __restrict__ out) {
    __shared__ float red[1024];
    int t = threadIdx.x;
    float perp = 0.0f;
    for (int n = 0; n < 4; n++) {
        float c = (float)g_cnt[n * Mm + t];
        float raw = DECAYF * ema_count[n * Mm + t] + (1.0f - DECAYF) * c;
        red[t] = raw; __syncthreads();
        for (int s = 512; s > 0; s >>= 1) { if (t < s) red[t] += red[t + s]; __syncthreads(); }
        float nsum = red[0]; __syncthreads();
        float fin = (raw + EPSF) / (nsum + Mm * EPSF) * nsum;
        out[OFF_CNT + n * Mm + t] = fin;
        g_fcnt[n * Mm + t] = fin;
        float avg = c * (1.0f / 65536.0f);
        float term = avg * logf(avg + 1e-10f);
        red[t] = term; __syncthreads();
        for (int s = 512; s > 0; s >>= 1) { if (t < s) red[t] += red[t + s]; __syncthreads(); }
        if (t == 0) perp += expf(-red[0]);
        __syncthreads();
    }
    if (t == 0) out[OFF_PERP] = perp;
}

// ---------------------------------------------------------------------------
// new_ema_weight and new_embedding
__global__ void k_weight(const float* __restrict__ ema_weight, float* __restrict__ out) {
    int i = blockIdx.x * 256 + threadIdx.x;          // < 262144
    float w = DECAYF * ema_weight[i] + (1.0f - DECAYF) * g_dw[i];
    out[OFF_EMW + i] = w;
    out[OFF_EMB + i] = w / g_fcnt[i >> 6];
}

// ---------------------------------------------------------------------------
// Gather quantized vectors, write z_q & encodings_zq, loss partials.
__global__ void k_gather(const float* __restrict__ x, const float* __restrict__ emb,
                         float* __restrict__ out) {
    __shared__ float se[16][68];    // se[l][d]
    __shared__ float red[256];
    int bn = blockIdx.x;
    int b = bn >> 2, n = bn & 3;
    int t = threadIdx.x;
    int r = t >> 4, c = t & 15;
    int idx = g_idx[n * BL + b * 16 + r];
    const float4* ep = (const float4*)emb + ((long long)n * Mm + idx) * 16;
    float4 v = ep[c];
    se[r][c * 4] = v.x; se[r][c * 4 + 1] = v.y; se[r][c * 4 + 2] = v.z; se[r][c * 4 + 3] = v.w;
    __syncthreads();
    long long base = (long long)b * 4096 + n * 1024;
    float4 xv = ((const float4*)(x + base))[t];
    int lin = t * 4;                             // lin = d*16 + l
    int d = lin >> 4, l0 = lin & 15;
    float q0 = se[l0 + 0][d], q1 = se[l0 + 1][d], q2 = se[l0 + 2][d], q3 = se[l0 + 3][d];
    ((float4*)(out + OFF_ZQ + base))[t] = make_float4(q0, q1, q2, q3);
    float2* ez = (float2*)(out + OFF_EZQ + base);   // OFF_EZQ only 8B-aligned
    ez[2 * t]     = make_float2(q0, q1);
    ez[2 * t + 1] = make_float2(q2, q3);
    float d0 = xv.x - q0, d1 = xv.y - q1, d2 = xv.z - q2, d3 = xv.w - q3;
    red[t] = d0 * d0 + d1 * d1 + d2 * d2 + d3 * d3;
    __syncthreads();
    for (int s = 128; s > 0; s >>= 1) { if (t < s) red[t] += red[t + s]; __syncthreads(); }
    if (t == 0) g_losspart[bn] = red[0];
}

// ---------------------------------------------------------------------------
__global__ void k_loss(float* __restrict__ out) {
    __shared__ float red[1024];
    int t = threadIdx.x;
    float s = 0.0f;
    for (int i = t; i < Bb * Nn; i += 1024) s += g_losspart[i];
    red[t] = s; __syncthreads();
    for (int st = 512; st > 0; st >>= 1) { if (t < st) red[t] += red[t + st]; __syncthreads(); }
    if (t == 0) out[OFF_LOSS] = COMMITF * red[0] / 16777216.0f;
}

// ---------------------------------------------------------------------------
extern "C" void kernel_launch(void* const* d_in, const int* in_sizes, int n_in,
                              void* d_out, int out_size) {
    const float* x          = (const float*)d_in[0];
    const float* emb        = (const float*)d_in[1];
    const float* ema_count  = (const float*)d_in[2];
    const float* ema_weight = (const float*)d_in[3];
    float* out = (float*)d_out;

    const int smem_bytes = SM_TOT * 4;   // 70656
    cudaFuncSetAttribute(k_argmin, cudaFuncAttributeMaxDynamicSharedMemorySize, smem_bytes);

    k_zero<<<1024, 256>>>();
    k_transpose<<<Bb * Nn, 256>>>(x);
    k_enorm<<<16, 256>>>(emb);
    dim3 ga(BL / 128, Nn);
    k_argmin<<<ga, 256, smem_bytes>>>(emb, out);
    k_dw<<<(Nn * BL) / 8, 256>>>();
    k_ema<<<1, 1024>>>(ema_count, out);
    k_weight<<<1024, 256>>>(ema_weight, out);
    k_gather<<<Bb * Nn, 256>>>(x, emb, out);
    k_loss<<<1, 1024>>>(out);
}

// round 6
// speedup vs baseline: 1.1979x; 1.0004x over previous
#include <cuda_runtime.h>
#include <cstdint>

// Problem constants
#define Nn 4
#define Mm 1024
#define Dd 64
#define Ll 16
#define Bb 4096
#define BL 65536           // Bb * Ll
#define DECAYF 0.999f
#define EPSF 1e-5f
#define COMMITF 0.05f

// Output layout (all fp32, concatenated in reference-return order)
#define OFF_ZQ   0LL
#define OFF_LOSS 16777216LL
#define OFF_PERP 16777217LL
#define OFF_IDX  16777218LL   // (B, N, L) as floats
#define OFF_EZQ  17039362LL   // identical values to z_q
#define OFF_EMB  33816578LL
#define OFF_CNT  34078722LL
#define OFF_EMW  34082818LL

// Device scratch (static allocation only — no cudaMalloc allowed)
__device__ float g_xt[Nn * BL * Dd];      // x transposed to (n, k, d) contiguous
__device__ float g_xnorm[Nn * BL];        // ||x_k||^2, reference rounding
__device__ int   g_idx[Nn * BL];          // argmin indices
__device__ float g_dw[Nn * Mm * Dd];      // scatter accumulator
__device__ int   g_cnt[Nn * Mm];          // histogram
__device__ float g_enorm[Nn * Mm];        // ||e||^2, reference rounding
__device__ float g_fcnt[Nn * Mm];         // final (laplace-smoothed) counts
__device__ float g_losspart[Bb * Nn];     // per-block loss partials

// cp.async helpers
#define CP_ASYNC16(dst, src) \
    asm volatile("cp.async.cg.shared.global [%0], [%1], 16;" :: "r"(dst), "l"(src))
#define CP_ASYNC4(dst, src) \
    asm volatile("cp.async.ca.shared.global [%0], [%1], 4;" :: "r"(dst), "l"(src))
#define CP_COMMIT() asm volatile("cp.async.commit_group;" ::: "memory")
#define CP_WAIT(nconst) asm volatile("cp.async.wait_group %0;" :: "n"(nconst) : "memory")

// ---------------------------------------------------------------------------
__global__ void k_zero() {
    int i = blockIdx.x * 256 + threadIdx.x;          // grid 1024 x 256 = 262144
    if (i < Nn * Mm * Dd) g_dw[i] = 0.0f;
    if (i < Nn * Mm)      g_cnt[i] = 0;
}

// ---------------------------------------------------------------------------
// Transpose x (B, N*D*L) -> g_xt (N, BL, D), and compute ||x||^2 per row with
// the exact reference rounding: sequential sum of individually-rounded squares.
__global__ void k_transpose(const float* __restrict__ x) {
    __shared__ float s[16][65];   // s[l][d]
    int bn = blockIdx.x;
    int b = bn >> 2, n = bn & 3;
    int t = threadIdx.x;
    const float4* xp = (const float4*)(x + (long long)b * 4096 + n * 1024);
    float4 v = xp[t];                      // lin = 4t : d = t>>2, l = (t&3)*4 .. +3
    int d = t >> 2, lb = (t & 3) * 4;
    s[lb + 0][d] = v.x; s[lb + 1][d] = v.y; s[lb + 2][d] = v.z; s[lb + 3][d] = v.w;
    __syncthreads();
    int r = t >> 4, c = t & 15;            // row l = r, 16 float4 per row
    float4 w = make_float4(s[r][c * 4], s[r][c * 4 + 1], s[r][c * 4 + 2], s[r][c * 4 + 3]);
    ((float4*)g_xt)[((long long)n * BL + b * 16 + r) * 16 + c] = w;
    if (t < 16) {
        float acc = 0.0f;
        #pragma unroll 8
        for (int dd = 0; dd < 64; dd++) {
            float vv = s[t][dd];
            acc = __fadd_rn(acc, __fmul_rn(vv, vv));   // square rounds, then add
        }
        g_xnorm[(long long)n * BL + b * 16 + t] = acc;
    }
}

// ---------------------------------------------------------------------------
// ||e||^2 per (n, m) with reference rounding (sequential add of rounded squares)
__global__ void k_enorm(const float* __restrict__ emb) {
    int i = blockIdx.x * blockDim.x + threadIdx.x;   // 0..4095
    const float* e = emb + (long long)i * 64;
    float s = 0.0f;
    #pragma unroll 8
    for (int d = 0; d < 64; d++) {
        float v = e[d];
        s = __fadd_rn(s, __fmul_rn(v, v));
    }
    g_enorm[i] = s;
}

// ---------------------------------------------------------------------------
// Main argmin GEMM, cp.async double-buffered.
// Block 256 threads (tx=m 16, ty=k 16). 128 k-rows per block; M swept in 16
// tiles of 64 codes, next tile prefetched with cp.async while current computes.
// Thread tile: 8 k (rows i*16+ty) x 4 m (cols j*16+tx).
// Shared rows stride 68 floats (16B-aligned, LDS.128-friendly).
// Score replicates reference bit-exactly:
//   score = fl( fl(Sx + Se) - 2*dot ),  dot = sequential-ascending-d fma chain.
#define XS_STR 68
#define SM_XS   0
#define SM_ES   (128 * XS_STR)                 // 2 buffers of [64][68]
#define SM_ENS  (SM_ES + 2 * 64 * XS_STR)      // 2 buffers of [64]
#define SM_XNR  (SM_ENS + 128)                 // [128]
#define SM_TOT  (SM_XNR + 128)                 // 17664 floats = 70656 B

extern __shared__ float sm_argmin[];
__global__ void __launch_bounds__(256, 3)
k_argmin(const float* __restrict__ emb, float* __restrict__ out) {
    float* xs  = sm_argmin + SM_XS;
    float* es  = sm_argmin + SM_ES;
    float* ens = sm_argmin + SM_ENS;
    float* xnr = sm_argmin + SM_XNR;
    const int n = blockIdx.y;
    const int kbase = blockIdx.x * 128;
    const int t = threadIdx.x;
    const int tx = t & 15, ty = t >> 4;

    uint32_t es_smem  = (uint32_t)__cvta_generic_to_shared(es);
    uint32_t ens_smem = (uint32_t)__cvta_generic_to_shared(ens);
    const float* embn = emb + (long long)n * Mm * 64;

    // ---- prologue: start es tile 0 fetch (async) --------------------------
    {
        const float* ep = embn;                       // tile 0
        #pragma unroll
        for (int i = 0; i < 4; i++) {
            int idx4 = t + i * 256;                   // 0..1023 float4s
            int row = idx4 >> 4, c4 = idx4 & 15;
            CP_ASYNC16(es_smem + (uint32_t)((row * XS_STR + c4 * 4) * 4),
                       (const float4*)ep + idx4);
        }
        if (t < 64) CP_ASYNC4(ens_smem + (uint32_t)(t * 4), g_enorm + n * Mm + t);
        CP_COMMIT();
    }

    // ---- load xs tile + xnorms (plain, overlaps with async fetch) ---------
    {
        const float4* xtp4 = (const float4*)(g_xt + ((long long)n * BL + kbase) * 64);
        #pragma unroll
        for (int i = 0; i < 8; i++) {
            int idx4 = t + i * 256;                   // 0..2047
            int row = idx4 >> 4, c4 = idx4 & 15;
            *(float4*)&xs[row * XS_STR + c4 * 4] = xtp4[idx4];
        }
        if (t < 128) xnr[t] = g_xnorm[(long long)n * BL + kbase + t];
    }

    float bv[8]; int bi[8];
    #pragma unroll
    for (int i = 0; i < 8; i++) { bv[i] = 3.4e38f; bi[i] = 0; }

    __syncthreads();                                  // xs/xnr visible
    float xnreg[8];
    #pragma unroll
    for (int i = 0; i < 8; i++) xnreg[i] = xnr[i * 16 + ty];

    for (int mt = 0; mt < 16; mt++) {
        int cur = mt & 1;
        // prefetch next tile into other buffer
        if (mt < 15) {
            const float* ep = embn + (mt + 1) * 64 * 64;
            uint32_t eb = es_smem + (uint32_t)((cur ^ 1) * 64 * XS_STR * 4);
            #pragma unroll
            for (int i = 0; i < 4; i++) {
                int idx4 = t + i * 256;
                int row = idx4 >> 4, c4 = idx4 & 15;
                CP_ASYNC16(eb + (uint32_t)((row * XS_STR + c4 * 4) * 4),
                           (const float4*)ep + idx4);
            }
            if (t < 64) CP_ASYNC4(ens_smem + (uint32_t)(((cur ^ 1) * 64 + t) * 4),
                                  g_enorm + n * Mm + (mt + 1) * 64 + t);
            CP_COMMIT();
            CP_WAIT(1);                               // tile mt arrived
        } else {
            CP_WAIT(0);
        }
        __syncthreads();

        const float* esb = es + cur * 64 * XS_STR;
        float acc[8][4];
        #pragma unroll
        for (int i = 0; i < 8; i++)
            #pragma unroll
            for (int j = 0; j < 4; j++) acc[i][j] = 0.0f;

        #pragma unroll 4
        for (int d4 = 0; d4 < 64; d4 += 4) {
            float4 e4[4];
            #pragma unroll
            for (int j = 0; j < 4; j++)
                e4[j] = *(const float4*)&esb[(j * 16 + tx) * XS_STR + d4];
            #pragma unroll
            for (int i = 0; i < 8; i++) {
                float4 x4 = *(const float4*)&xs[(i * 16 + ty) * XS_STR + d4];
                #pragma unroll
                for (int j = 0; j < 4; j++) {
                    acc[i][j] = __fmaf_rn(x4.x, e4[j].x, acc[i][j]);
                    acc[i][j] = __fmaf_rn(x4.y, e4[j].y, acc[i][j]);
                    acc[i][j] = __fmaf_rn(x4.z, e4[j].z, acc[i][j]);
                    acc[i][j] = __fmaf_rn(x4.w, e4[j].w, acc[i][j]);
                }
            }
        }

        // reference-exact score + running argmin (m ascending => '<' keeps first)
        #pragma unroll
        for (int j = 0; j < 4; j++) {
            int ml = j * 16 + tx;
            float en = ens[cur * 64 + ml];
            int mg = mt * 64 + ml;
            #pragma unroll
            for (int i = 0; i < 8; i++) {
                float t1 = __fadd_rn(xnreg[i], en);
                float sc = __fadd_rn(t1, __fmul_rn(-2.0f, acc[i][j]));
                if (sc < bv[i]) { bv[i] = sc; bi[i] = mg; }
            }
        }
        __syncthreads();   // all reads of buf cur done before it is refilled
    }

    // cross-thread reduction over the 16 tx lanes per k (tie -> lowest index)
    float* rv = sm_argmin;                  // [128][16]
    int*   ri = (int*)(sm_argmin + 2048);   // [128][16]
    #pragma unroll
    for (int i = 0; i < 8; i++) {
        rv[(i * 16 + ty) * 16 + tx] = bv[i];
        ri[(i * 16 + ty) * 16 + tx] = bi[i];
    }
    __syncthreads();
    if (t < 128) {
        float best = rv[t * 16]; int besti = ri[t * 16];
        #pragma unroll
        for (int q = 1; q < 16; q++) {
            float v = rv[t * 16 + q]; int ii = ri[t * 16 + q];
            if (v < best || (v == best && ii < besti)) { best = v; besti = ii; }
        }
        int kg = kbase + t;
        g_idx[n * BL + kg] = besti;
        atomicAdd(&g_cnt[n * Mm + besti], 1);
        int b = kg >> 4, l = kg & 15;
        out[OFF_IDX + ((long long)b * Nn + n) * Ll + l] = (float)besti;
    }
}

// ---------------------------------------------------------------------------
// dw[n, m, :] += x_flat[n, k, :] for each k with idx==m. One warp per row.
__global__ void k_dw() {
    int gw = (blockIdx.x * blockDim.x + threadIdx.x) >> 5;
    int lane = threadIdx.x & 31;
    if (gw >= Nn * BL) return;
    int n = gw >> 16;
    int m = g_idx[gw];
    const float* xr = g_xt + (long long)gw * 64;
    float* dwp = g_dw + ((long long)n * Mm + m) * 64;
    atomicAdd(dwp + lane,      xr[lane]);
    atomicAdd(dwp + lane + 32, xr[lane + 32]);
}

// ---------------------------------------------------------------------------
// EMA counts + laplace smoothing + perplexity. One block, 1024 threads (m=t).
__global__ void k_ema(const float* __restrict__ ema_count, float* __restrict__ out) {
    __shared__ float red[1024];
    int t = threadIdx.x;
    float perp = 0.0f;
    for (int n = 0; n < 4; n++) {
        float c = (float)g_cnt[n * Mm + t];
        float raw = DECAYF * ema_count[n * Mm + t] + (1.0f - DECAYF) * c;
        red[t] = raw; __syncthreads();
        for (int s = 512; s > 0; s >>= 1) { if (t < s) red[t] += red[t + s]; __syncthreads(); }
        float nsum = red[0]; __syncthreads();
        float fin = (raw + EPSF) / (nsum + Mm * EPSF) * nsum;
        out[OFF_CNT + n * Mm + t] = fin;
        g_fcnt[n * Mm + t] = fin;
        float avg = c * (1.0f / 65536.0f);
        float term = avg * logf(avg + 1e-10f);
        red[t] = term; __syncthreads();
        for (int s = 512; s > 0; s >>= 1) { if (t < s) red[t] += red[t + s]; __syncthreads(); }
        if (t == 0) perp += expf(-red[0]);
        __syncthreads();
    }
    if (t == 0) out[OFF_PERP] = perp;
}

// ---------------------------------------------------------------------------
// new_ema_weight and new_embedding
__global__ void k_weight(const float* __restrict__ ema_weight, float* __restrict__ out) {
    int i = blockIdx.x * 256 + threadIdx.x;          // < 262144
    float w = DECAYF * ema_weight[i] + (1.0f - DECAYF) * g_dw[i];
    out[OFF_EMW + i] = w;
    out[OFF_EMB + i] = w / g_fcnt[i >> 6];
}

// ---------------------------------------------------------------------------
// Gather quantized vectors, write z_q & encodings_zq, loss partials.
__global__ void k_gather(const float* __restrict__ x, const float* __restrict__ emb,
                         float* __restrict__ out) {
    __shared__ float se[16][68];    // se[l][d]
    __shared__ float red[256];
    int bn = blockIdx.x;
    int b = bn >> 2, n = bn & 3;
    int t = threadIdx.x;
    int r = t >> 4, c = t & 15;
    int idx = g_idx[n * BL + b * 16 + r];
    const float4* ep = (const float4*)emb + ((long long)n * Mm + idx) * 16;
    float4 v = ep[c];
    se[r][c * 4] = v.x; se[r][c * 4 + 1] = v.y; se[r][c * 4 + 2] = v.z; se[r][c * 4 + 3] = v.w;
    __syncthreads();
    long long base = (long long)b * 4096 + n * 1024;
    float4 xv = ((const float4*)(x + base))[t];
    int lin = t * 4;                             // lin = d*16 + l
    int d = lin >> 4, l0 = lin & 15;
    float q0 = se[l0 + 0][d], q1 = se[l0 + 1][d], q2 = se[l0 + 2][d], q3 = se[l0 + 3][d];
    ((float4*)(out + OFF_ZQ + base))[t] = make_float4(q0, q1, q2, q3);
    float2* ez = (float2*)(out + OFF_EZQ + base);   // OFF_EZQ only 8B-aligned
    ez[2 * t]     = make_float2(q0, q1);
    ez[2 * t + 1] = make_float2(q2, q3);
    float d0 = xv.x - q0, d1 = xv.y - q1, d2 = xv.z - q2, d3 = xv.w - q3;
    red[t] = d0 * d0 + d1 * d1 + d2 * d2 + d3 * d3;
    __syncthreads();
    for (int s = 128; s > 0; s >>= 1) { if (t < s) red[t] += red[t + s]; __syncthreads(); }
    if (t == 0) g_losspart[bn] = red[0];
}

// ---------------------------------------------------------------------------
__global__ void k_loss(float* __restrict__ out) {
    __shared__ float red[1024];
    int t = threadIdx.x;
    float s = 0.0f;
    for (int i = t; i < Bb * Nn; i += 1024) s += g_losspart[i];
    red[t] = s; __syncthreads();
    for (int st = 512; st > 0; st >>= 1) { if (t < st) red[t] += red[t + st]; __syncthreads(); }
    if (t == 0) out[OFF_LOSS] = COMMITF * red[0] / 16777216.0f;
}

// ---------------------------------------------------------------------------
extern "C" void kernel_launch(void* const* d_in, const int* in_sizes, int n_in,
                              void* d_out, int out_size) {
    const float* x          = (const float*)d_in[0];
    const float* emb        = (const float*)d_in[1];
    const float* ema_count  = (const float*)d_in[2];
    const float* ema_weight = (const float*)d_in[3];
    float* out = (float*)d_out;

    const int smem_bytes = SM_TOT * 4;   // 70656
    cudaFuncSetAttribute(k_argmin, cudaFuncAttributeMaxDynamicSharedMemorySize, smem_bytes);

    k_zero<<<1024, 256>>>();
    k_transpose<<<Bb * Nn, 256>>>(x);
    k_enorm<<<16, 256>>>(emb);
    dim3 ga(BL / 128, Nn);
    k_argmin<<<ga, 256, smem_bytes>>>(emb, out);
    k_dw<<<(Nn * BL) / 8, 256>>>();
    k_ema<<<1, 1024>>>(ema_count, out);
    k_weight<<<1024, 256>>>(ema_weight, out);
    k_gather<<<Bb * Nn, 256>>>(x, emb, out);
    k_loss<<<1, 1024>>>(out);
}